// round 16
// baseline (speedup 1.0000x reference)
#include <cuda_runtime.h>
#include <cuda_bf16.h>

#define NQ 4
#define DIM 16
#define NGATES 16      // NUM_LAYERS * NQ
#define NUM_LAYERS 4
#define THREADS 256

// Single fused kernel. EVERY block builds the 16-entry lookup table itself in
// shared memory (all-warp parallel shuffle chain) — no cross-block sync, no
// flag, no PDL, no second kernel. The build's ALU/SHFL work hides in the
// latency shadow of the gather's memory traffic (issue util was only ~13%).
__global__ void __launch_bounds__(THREADS)
vqc_all(const float* __restrict__ wa,   // (4,2,3)
        const float* __restrict__ wb,   // (4,2,3)
        const float* __restrict__ sa,   // (2,)
        const float* __restrict__ sb,   // (2,)
        const int2*  __restrict__ x1,
        const int2*  __restrict__ x2,
        float4*      __restrict__ out,
        int n) {
    const int tid = threadIdx.x;
    const int gid = blockIdx.x * THREADS + tid;

    // Prefetch this thread's element first: DRAM/L2 latency overlaps the
    // whole table build below.
    int2 a, c;
    const bool v = (gid < n);
    if (v) { a = x1[gid]; c = x2[gid]; }

    __shared__ float  U[NGATES][8];   // per-gate 2x2 unitary
    __shared__ float4 stab[DIM];      // the lookup table

    // ---- Phase 1: warp 0 computes all 16 gate unitaries (parallel sincos) ----
    if (tid < NGATES) {
        int l = tid >> 2, wire = tid & 3;
        const float* p = (wire < 2) ? (wa + l * 6 + wire * 3)
                                    : (wb + l * 6 + (wire - 2) * 3);
        float phi = p[0], theta = p[1], omega = p[2];
        float cc, s;    __sincosf(theta * 0.5f, &s, &cc);
        float sm, cm;   __sincosf(-0.5f * (phi + omega), &sm, &cm);
        float sp, cp;   __sincosf( 0.5f * (phi + omega), &sp, &cp);
        float sdm, cdm; __sincosf(-0.5f * (phi - omega), &sdm, &cdm);
        float sdp, cdp; __sincosf( 0.5f * (phi - omega), &sdp, &cdp);
        U[tid][0] = cm * cc;   U[tid][1] = sm * cc;     // U00
        U[tid][2] = -cdp * s;  U[tid][3] = -sdp * s;    // U01
        U[tid][4] = cdm * s;   U[tid][5] = sdm * s;     // U10
        U[tid][6] = cp * cc;   U[tid][7] = sp * cc;     // U11
    }
    __syncthreads();

    // ---- Phase 2: ALL 8 warps evolve 2 columns each (16 cols total) ----
    const int lane = tid & 31;
    const int wid  = tid >> 5;
    const int idx  = lane & 15;                 // amplitude index
    const int col  = (wid << 1) | (lane >> 4);  // initial basis state
    float re = (idx == col) ? 1.0f : 0.0f;
    float im = 0.0f;

#pragma unroll
    for (int l = 0; l < NUM_LAYERS; l++) {
#pragma unroll
        for (int wire = 0; wire < NQ; wire++) {
            const int g = l * 4 + wire;
            const int m = 1 << (NQ - 1 - wire);
            float pre = __shfl_xor_sync(0xFFFFFFFFu, re, m);
            float pim = __shfl_xor_sync(0xFFFFFFFFu, im, m);
            bool hi = (idx & m) != 0;
            float Xr = hi ? U[g][6] : U[g][0];
            float Xi = hi ? U[g][7] : U[g][1];
            float Yr = hi ? U[g][4] : U[g][2];
            float Yi = hi ? U[g][5] : U[g][3];
            float nre = Xr * re - Xi * im + Yr * pre - Yi * pim;
            float nim = Xr * im + Xi * re + Yr * pim + Yi * pre;
            re = nre; im = nim;
        }
        // The 4 CNOT perms composed into ONE shuffle:
        // final[i] = orig[src0(src1(src2(src3(i))))]
        // gate g: src_g(i) = i ^ (bit_cb(i) << tb); (cb,tb) = (3,2),(1,0),(3,1),(3,0)
        {
            int t = idx;
            t ^= ((t >> 3) & 1) << 0;   // g3: cb=3, tb=0
            t ^= ((t >> 3) & 1) << 1;   // g2: cb=3, tb=1
            t ^= ((t >> 1) & 1) << 0;   // g1: cb=1, tb=0
            t ^= ((t >> 3) & 1) << 2;   // g0: cb=3, tb=2
            int srcLane = (lane & 0x10) | t;
            re = __shfl_sync(0xFFFFFFFFu, re, srcLane);
            im = __shfl_sync(0xFFFFFFFFu, im, srcLane);
        }
    }

    // ---- Z-expectations: 16-lane butterfly ----
    float p = re * re + im * im;
    float z0 = ((idx >> 3) & 1) ? -p : p;
    float z1 = ((idx >> 2) & 1) ? -p : p;
    float z2 = ((idx >> 1) & 1) ? -p : p;
    float z3 = ( idx       & 1) ? -p : p;
#pragma unroll
    for (int off = 1; off < 16; off <<= 1) {
        z0 += __shfl_xor_sync(0xFFFFFFFFu, z0, off);
        z1 += __shfl_xor_sync(0xFFFFFFFFu, z1, off);
        z2 += __shfl_xor_sync(0xFFFFFFFFu, z2, off);
        z3 += __shfl_xor_sync(0xFFFFFFFFu, z3, off);
    }
    if (idx == 0) {   // lanes 0 and 16 of each warp -> 16 writers, 16 cols
        float4 r;
        r.x = (z0 + 1.0f) * 0.5f * sa[0];
        r.y = (z1 + 1.0f) * 0.5f * sa[1];
        r.z = (z2 + 1.0f) * 0.5f * sb[0];
        r.w = (z3 + 1.0f) * 0.5f * sb[1];
        stab[col] = r;
    }
    __syncthreads();

    // ---- Gather: 1 elem/thread, table from SMEM ----
    if (v) {
        out[gid] = stab[(a.x << 3) | (a.y << 2) | (c.x << 1) | c.y];
    }
}

extern "C" void kernel_launch(void* const* d_in, const int* in_sizes, int n_in,
                              void* d_out, int out_size) {
    const int2*  x1 = (const int2*) d_in[0];
    const int2*  x2 = (const int2*) d_in[1];
    const float* wa = (const float*)d_in[2];
    const float* wb = (const float*)d_in[3];
    const float* sa = (const float*)d_in[4];
    const float* sb = (const float*)d_in[5];
    float4* out = (float4*)d_out;

    int batch = in_sizes[0] / 2;   // x1 is (BATCH, 2) int32
    int blocks = (batch + THREADS - 1) / THREADS;
    if (blocks < 1) blocks = 1;

    vqc_all<<<blocks, THREADS>>>(wa, wb, sa, sb, x1, x2, out, batch);
}

// round 17
// speedup vs baseline: 1.5529x; 1.5529x over previous
#include <cuda_runtime.h>
#include <cuda_bf16.h>

#define NQ 4
#define DIM 16
#define NGATES 16      // NUM_LAYERS * NQ
#define NUM_LAYERS 4
#define THREADS 256

__device__ float4 g_table[DIM];

// ===================== Builder: 1 block, shuffle-parallel =====================
// CNOT permutations are linear over GF(2)^4 and the per-layer composite has
// order 4 (Lambda^4 = I). We therefore never shuffle amplitudes for CNOTs:
// the lane->logical frame is tracked implicitly via compile-time shfl masks
// XM[g] = Lambda^{layer-1}(wire_mask) and hi/lo parity masks PM[g].
__global__ void __launch_bounds__(THREADS)
vqc_build(const float* __restrict__ wa,   // (4,2,3)
          const float* __restrict__ wb,   // (4,2,3)
          const float* __restrict__ sa,   // (2,)
          const float* __restrict__ sb) { // (2,)
    __shared__ float U[NGATES][8];
    const int tid = threadIdx.x;

    if (tid < NGATES) {
        int l = tid >> 2, wire = tid & 3;
        const float* p = (wire < 2) ? (wa + l * 6 + wire * 3)
                                    : (wb + l * 6 + (wire - 2) * 3);
        float phi = p[0], theta = p[1], omega = p[2];
        float cc, s;    __sincosf(theta * 0.5f, &s, &cc);
        float sm, cm;   __sincosf(-0.5f * (phi + omega), &sm, &cm);
        float sp, cp;   __sincosf( 0.5f * (phi + omega), &sp, &cp);
        float sdm, cdm; __sincosf(-0.5f * (phi - omega), &sdm, &cdm);
        float sdp, cdp; __sincosf( 0.5f * (phi - omega), &sdp, &cdp);
        U[tid][0] = cm * cc;   U[tid][1] = sm * cc;     // U00
        U[tid][2] = -cdp * s;  U[tid][3] = -sdp * s;    // U01
        U[tid][4] = cdm * s;   U[tid][5] = sdm * s;     // U10
        U[tid][6] = cp * cc;   U[tid][7] = sp * cc;     // U11
    }
    __syncthreads();

    // 16 columns x 16 amplitudes: one complex amplitude per thread.
    const int idx  = tid & 15;
    const int col  = tid >> 4;
    float re = (idx == col) ? 1.0f : 0.0f;
    float im = 0.0f;

    // Per-gate shfl.xor masks (frame-transformed wire masks) and hi-parity
    // masks, layers 1..4 x wires 0..3. Derived from Lambda powers:
    // Lambda: b3'=b3, b2'=b2^b3, b1'=b1^b3, b0'=b0^b1;  Lambda^4 = I.
    const int XM[NGATES] = { 8, 4, 2, 1,   14, 4, 3, 1,
                             9, 4, 2, 1,   15, 4, 3, 1 };
    const int PM[NGATES] = { 8, 4, 2, 1,    8,12,10,11,
                             8, 4, 2, 9,    8,12,10, 3 };

#pragma unroll
    for (int g = 0; g < NGATES; g++) {
        float pre = __shfl_xor_sync(0xFFFFFFFFu, re, XM[g]);
        float pim = __shfl_xor_sync(0xFFFFFFFFu, im, XM[g]);
        bool hi = (__popc(idx & PM[g]) & 1) != 0;
        float Xr = hi ? U[g][6] : U[g][0];
        float Xi = hi ? U[g][7] : U[g][1];
        float Yr = hi ? U[g][4] : U[g][2];
        float Yi = hi ? U[g][5] : U[g][3];
        float nre = Xr * re - Xi * im + Yr * pre - Yi * pim;
        float nim = Xr * im + Xi * re + Yr * pim + Yi * pre;
        re = nre; im = nim;
    }
    // Frame returned to identity (Lambda^4 = I): lane `idx` holds amplitude
    // of basis state `idx` — Z-signs use idx directly.

    float p = re * re + im * im;
    float z0 = ((idx >> 3) & 1) ? -p : p;
    float z1 = ((idx >> 2) & 1) ? -p : p;
    float z2 = ((idx >> 1) & 1) ? -p : p;
    float z3 = ( idx       & 1) ? -p : p;
#pragma unroll
    for (int off = 1; off < 16; off <<= 1) {
        z0 += __shfl_xor_sync(0xFFFFFFFFu, z0, off);
        z1 += __shfl_xor_sync(0xFFFFFFFFu, z1, off);
        z2 += __shfl_xor_sync(0xFFFFFFFFu, z2, off);
        z3 += __shfl_xor_sync(0xFFFFFFFFu, z3, off);
    }
    if (idx == 0) {
        float4 r;
        r.x = (z0 + 1.0f) * 0.5f * sa[0];
        r.y = (z1 + 1.0f) * 0.5f * sa[1];
        r.z = (z2 + 1.0f) * 0.5f * sb[0];
        r.w = (z3 + 1.0f) * 0.5f * sb[1];
        g_table[col] = r;
    }
    __syncthreads();
    __threadfence();
    asm volatile("griddepcontrol.launch_dependents;" ::: "memory");
}

// ===================== Gather: PDL-dependent, 1 elem/thread ===================
__global__ void __launch_bounds__(THREADS)
vqc_gather(const int2* __restrict__ x1,
           const int2* __restrict__ x2,
           float4* __restrict__ out,
           int n) {
    const int gid = blockIdx.x * THREADS + threadIdx.x;

    // Input loads issued before the PDL wait: latency overlaps the builder.
    int2 a, c;
    bool v = (gid < n);
    if (v) { a = x1[gid]; c = x2[gid]; }

    asm volatile("griddepcontrol.wait;" ::: "memory");

    if (v) {
        out[gid] = g_table[(a.x << 3) | (a.y << 2) | (c.x << 1) | c.y];
    }
}

extern "C" void kernel_launch(void* const* d_in, const int* in_sizes, int n_in,
                              void* d_out, int out_size) {
    const int2*  x1 = (const int2*) d_in[0];
    const int2*  x2 = (const int2*) d_in[1];
    const float* wa = (const float*)d_in[2];
    const float* wb = (const float*)d_in[3];
    const float* sa = (const float*)d_in[4];
    const float* sb = (const float*)d_in[5];
    float4* out = (float4*)d_out;

    int batch = in_sizes[0] / 2;   // x1 is (BATCH, 2) int32
    int blocks = (batch + THREADS - 1) / THREADS;
    if (blocks < 1) blocks = 1;

    vqc_build<<<1, THREADS>>>(wa, wb, sa, sb);

    cudaLaunchConfig_t cfg = {};
    cfg.gridDim  = dim3((unsigned)blocks, 1, 1);
    cfg.blockDim = dim3(THREADS, 1, 1);
    cfg.dynamicSmemBytes = 0;
    cfg.stream = 0;
    cudaLaunchAttribute attrs[1];
    attrs[0].id = cudaLaunchAttributeProgrammaticStreamSerialization;
    attrs[0].val.programmaticStreamSerializationAllowed = 1;
    cfg.attrs = attrs;
    cfg.numAttrs = 1;

    cudaError_t err = cudaLaunchKernelEx(&cfg, vqc_gather, x1, x2, out, batch);
    if (err != cudaSuccess) {
        // Fallback: plain launch (griddepcontrol.wait is a no-op without PDL).
        vqc_gather<<<blocks, THREADS>>>(x1, x2, out, batch);
    }
}